// round 7
// baseline (speedup 1.0000x reference)
#include <cuda_runtime.h>
#include <cuda_bf16.h>
#include <cuda_fp16.h>
#include <math.h>
#include <stdint.h>

#define NTHREADS 256
#define NWARPS 8
#define TILE_M 256     // 8 warps x 32 points

// fixed problem geometry
#define C_STRIDE 2097152ULL     // 256*256*32
#define B_STRIDE 67108864ULL    // 32*256*256*32
#define I_STRIDE 8192
#define J_STRIDE 32

// B-fragment banks: [hi/lo][ (nt*4+kf)*32*2 + lane*2 + w ]
struct __align__(16) Smem {
  unsigned wz_h[2][2048];
  unsigned wr_h[2][2048];
  unsigned wq_h[2][2048];
  unsigned wz_x[2][2048];
  unsigned wr_x[2][2048];
  unsigned wq_x[2][2048];
  unsigned wd_h[2][1024];
  unsigned wd_x[2][1024];
  // xproj dumps, fp16x2: [warp][entry 0-27][tile 0/1][lane][2]
  unsigned xp[NWARPS][28][2][32][2];
  float bz[64], br[64], bq[64], bd1[32];
  float Wd2[96], bd2[4];
};

// ---- bf16 pack/unpack helpers ----
__device__ __forceinline__ float bfl(unsigned w) { return __uint_as_float(w << 16); }
__device__ __forceinline__ float bfh(unsigned w) { return __uint_as_float(w & 0xffff0000u); }
__device__ __forceinline__ unsigned packbf(float lo_, float hi_) {
  unsigned r;
  asm("cvt.rn.bf16x2.f32 %0, %1, %2;" : "=r"(r) : "f"(hi_), "f"(lo_));
  return r;
}
__device__ __forceinline__ void splitp(float v0, float v1, unsigned& hi, unsigned& lo) {
  unsigned h = packbf(v0, v1);
  float r0 = v0 - bfl(h), r1 = v1 - bfh(h);
  hi = h;
  lo = packbf(r0, r1);
}

__device__ __forceinline__ float sigm(float x) {
  return __fdividef(1.0f, 1.0f + __expf(-x));
}
__device__ __forceinline__ float tanhfast(float x) {
  return __fdividef(2.0f, 1.0f + __expf(-2.0f * x)) - 1.0f;
}

// ---- fp16 xp store/load ----
__device__ __forceinline__ void xp_store(unsigned* dst, const float d[4]) {
  __half2 a = __floats2half2_rn(d[0], d[1]);
  __half2 b = __floats2half2_rn(d[2], d[3]);
  dst[0] = *reinterpret_cast<unsigned*>(&a);
  dst[1] = *reinterpret_cast<unsigned*>(&b);
}
__device__ __forceinline__ void xp_load(float d[4], const unsigned* src) {
  uint2 v = *reinterpret_cast<const uint2*>(src);
  __half2 a = *reinterpret_cast<__half2*>(&v.x);
  __half2 b = *reinterpret_cast<__half2*>(&v.y);
  float2 fa = __half22float2(a), fb = __half22float2(b);
  d[0] = fa.x; d[1] = fa.y; d[2] = fb.x; d[3] = fb.y;
}

// warp HMMA m16n8k16 bf16 -> f32 accumulate
__device__ __forceinline__ void mma4(float d[4], const unsigned a[4], uint2 b) {
  asm volatile(
    "mma.sync.aligned.m16n8k16.row.col.f32.bf16.bf16.f32 "
    "{%0,%1,%2,%3}, {%4,%5,%6,%7}, {%8,%9}, {%0,%1,%2,%3};"
    : "+f"(d[0]), "+f"(d[1]), "+f"(d[2]), "+f"(d[3])
    : "r"(a[0]), "r"(a[1]), "r"(a[2]), "r"(a[3]), "r"(b.x), "r"(b.y));
}

// 12 HMMA per tile x 2 tiles, B frags loaded once
__device__ __forceinline__ void gemm12x2(
    float d0[4], float d1[4], const unsigned* whi, const unsigned* wlo,
    int nt, int lane,
    const unsigned (&A0H)[4][4], const unsigned (&A0L)[4][4],
    const unsigned (&A1H)[4][4], const unsigned (&A1L)[4][4]) {
#pragma unroll
  for (int kf = 0; kf < 4; kf++) {
    int o = ((nt * 4 + kf) * 32 + lane) * 2;
    uint2 bh = *(const uint2*)(whi + o);
    uint2 bl = *(const uint2*)(wlo + o);
    mma4(d0, A0H[kf], bh); mma4(d1, A1H[kf], bh);
    mma4(d0, A0L[kf], bh); mma4(d1, A1L[kf], bh);
    mma4(d0, A0H[kf], bl); mma4(d1, A1H[kf], bl);
  }
}

// fill one gate's B-fragment bank (hi+lo) from row-major W[n][128], cols koff..koff+63
__device__ __forceinline__ void fill_frag(unsigned* dst_hi, unsigned* dst_lo,
                                          const float* __restrict__ W, int koff,
                                          int ntn, int tid) {
  int total = ntn * 4 * 32 * 2;
  for (int i = tid; i < total; i += NTHREADS) {
    int w = i & 1;
    int lane = (i >> 1) & 31;
    int kf = (i >> 6) & 3;
    int nt = i >> 8;
    int n = nt * 8 + (lane >> 2);
    int k = kf * 16 + (lane & 3) * 2 + w * 8;
    float v0 = W[n * 128 + koff + k];
    float v1 = W[n * 128 + koff + k + 1];
    unsigned hw, lw;
    splitp(v0, v1, hw, lw);
    dst_hi[i] = hw;
    dst_lo[i] = lw;
  }
}

// gather h for a point pair (rowA=pt, rowB=pt+8) into A frags
__device__ __forceinline__ void gather_h(
    unsigned (&AH)[4][4], unsigned (&AL)[4][4],
    const float* __restrict__ before, const float* __restrict__ after,
    const int* __restrict__ coords, int pA, int pB, int N, int c2t) {
  const int* ccA = coords + (size_t)pA * 3;
  const int* ccB = coords + (size_t)pB * 3;
  int spA = ccA[0] * I_STRIDE + ccA[1] * J_STRIDE + ccA[2];
  int spB = ccB[0] * I_STRIDE + ccB[1] * J_STRIDE + ccB[2];
  const float* befA = before + (size_t)(pA / N) * B_STRIDE + (unsigned)spA;
  const float* aftA = after  + (size_t)(pA / N) * B_STRIDE + (unsigned)spA;
  const float* befB = before + (size_t)(pB / N) * B_STRIDE + (unsigned)spB;
  const float* aftB = after  + (size_t)(pB / N) * B_STRIDE + (unsigned)spB;
#pragma unroll
  for (int kf = 0; kf < 4; kf++) {
    int cb = (kf & 1) * 16 + c2t;
    const float* pa = (kf < 2) ? befA : aftA;
    const float* pb = (kf < 2) ? befB : aftB;
    float a0 = __ldg(pa + (size_t)cb * C_STRIDE);
    float a1 = __ldg(pa + (size_t)(cb + 1) * C_STRIDE);
    float a2 = __ldg(pa + (size_t)(cb + 8) * C_STRIDE);
    float a3 = __ldg(pa + (size_t)(cb + 9) * C_STRIDE);
    float b0 = __ldg(pb + (size_t)cb * C_STRIDE);
    float b1 = __ldg(pb + (size_t)(cb + 1) * C_STRIDE);
    float b2 = __ldg(pb + (size_t)(cb + 8) * C_STRIDE);
    float b3 = __ldg(pb + (size_t)(cb + 9) * C_STRIDE);
    splitp(a0, a1, AH[kf][0], AL[kf][0]);
    splitp(b0, b1, AH[kf][1], AL[kf][1]);
    splitp(a2, a3, AH[kf][2], AL[kf][2]);
    splitp(b2, b3, AH[kf][3], AL[kf][3]);
  }
}

__device__ __forceinline__ void load_x_frags(
    unsigned (&XH)[4][4], unsigned (&XL)[4][4],
    const float* __restrict__ pf, int pA, int pB, int lane) {
  const float2* xA = (const float2*)(pf + (size_t)pA * 64);
  const float2* xB = (const float2*)(pf + (size_t)pB * 64);
#pragma unroll
  for (int kf = 0; kf < 4; kf++) {
    float2 a0 = __ldg(xA + kf * 8 + (lane & 3));
    float2 a2 = __ldg(xA + kf * 8 + (lane & 3) + 4);
    float2 b0 = __ldg(xB + kf * 8 + (lane & 3));
    float2 b2 = __ldg(xB + kf * 8 + (lane & 3) + 4);
    splitp(a0.x, a0.y, XH[kf][0], XL[kf][0]);
    splitp(b0.x, b0.y, XH[kf][1], XL[kf][1]);
    splitp(a2.x, a2.y, XH[kf][2], XL[kf][2]);
    splitp(b2.x, b2.y, XH[kf][3], XL[kf][3]);
  }
}

__global__ __launch_bounds__(NTHREADS, 1)
void gru_hmma2_kernel(
    const float* __restrict__ before, const float* __restrict__ after,
    const float* __restrict__ pf, const int* __restrict__ coords,
    const float* __restrict__ Wz, const float* __restrict__ bz,
    const float* __restrict__ Wr, const float* __restrict__ br,
    const float* __restrict__ Wq, const float* __restrict__ bq,
    const float* __restrict__ Wd1, const float* __restrict__ bd1,
    const float* __restrict__ Wd2, const float* __restrict__ bd2,
    float* __restrict__ out, int N, int total_pts)
{
  extern __shared__ char smem_raw[];
  Smem& s = *reinterpret_cast<Smem*>(smem_raw);
  const int tid = threadIdx.x;
  const int wid = tid >> 5, lane = tid & 31;
  const int g = lane >> 2, c2t = (lane & 3) * 2;

  // ---- one-time weight fragment prep ----
  fill_frag(s.wz_h[0], s.wz_h[1], Wz, 0, 8, tid);
  fill_frag(s.wr_h[0], s.wr_h[1], Wr, 0, 8, tid);
  fill_frag(s.wq_h[0], s.wq_h[1], Wq, 0, 8, tid);
  fill_frag(s.wz_x[0], s.wz_x[1], Wz, 64, 8, tid);
  fill_frag(s.wr_x[0], s.wr_x[1], Wr, 64, 8, tid);
  fill_frag(s.wq_x[0], s.wq_x[1], Wq, 64, 8, tid);
  fill_frag(s.wd_h[0], s.wd_h[1], Wd1, 0, 4, tid);
  fill_frag(s.wd_x[0], s.wd_x[1], Wd1, 64, 4, tid);
  if (tid < 64) { s.bz[tid] = bz[tid]; s.br[tid] = br[tid]; s.bq[tid] = bq[tid]; }
  if (tid < 32) s.bd1[tid] = bd1[tid];
  if (tid < 96) s.Wd2[tid] = Wd2[tid];
  if (tid < 3)  s.bd2[tid] = bd2[tid];
  __syncthreads();

  const int ntiles = (total_pts + TILE_M - 1) / TILE_M;

  for (int tile = blockIdx.x; tile < ntiles; tile += gridDim.x) {
    const int ptA = tile * TILE_M + wid * 32 + g;   // tile0 rows 0-7
    const int ptB = ptA + 8;                         // tile0 rows 8-15
    const int ptC = ptA + 16;                        // tile1 rows 0-7
    const int ptD = ptA + 24;                        // tile1 rows 8-15
    const bool vA = ptA < total_pts, vB = ptB < total_pts;
    const bool vC = ptC < total_pts, vD = ptD < total_pts;
    const int last = total_pts - 1;
    const int pA = vA ? ptA : last, pB = vB ? ptB : last;
    const int pC = vC ? ptC : last, pD = vD ? ptD : last;

    // ---- gather h into A fragments ----
    unsigned A0H[4][4], A0L[4][4], A1H[4][4], A1L[4][4];
    gather_h(A0H, A0L, before, after, coords, pA, pB, N, c2t);
    gather_h(A1H, A1L, before, after, coords, pC, pD, N, c2t);

    // ---- x fragments + x-projection GEMMs -> fp16 smem dumps ----
    {
      unsigned X0H[4][4], X0L[4][4], X1H[4][4], X1L[4][4];
      load_x_frags(X0H, X0L, pf, pA, pB, lane);
      load_x_frags(X1H, X1L, pf, pC, pD, lane);
#pragma unroll
      for (int nt = 0; nt < 8; nt++) {
        int n0 = nt * 8 + c2t;
        float d0[4], d1[4];
        d0[0] = s.bz[n0]; d0[1] = s.bz[n0 + 1]; d0[2] = d0[0]; d0[3] = d0[1];
        d1[0] = d0[0]; d1[1] = d0[1]; d1[2] = d0[0]; d1[3] = d0[1];
        gemm12x2(d0, d1, s.wz_x[0], s.wz_x[1], nt, lane, X0H, X0L, X1H, X1L);
        xp_store(&s.xp[wid][nt][0][lane][0], d0);
        xp_store(&s.xp[wid][nt][1][lane][0], d1);
      }
#pragma unroll
      for (int nt = 0; nt < 8; nt++) {
        int n0 = nt * 8 + c2t;
        float d0[4], d1[4];
        d0[0] = s.br[n0]; d0[1] = s.br[n0 + 1]; d0[2] = d0[0]; d0[3] = d0[1];
        d1[0] = d0[0]; d1[1] = d0[1]; d1[2] = d0[0]; d1[3] = d0[1];
        gemm12x2(d0, d1, s.wr_x[0], s.wr_x[1], nt, lane, X0H, X0L, X1H, X1L);
        xp_store(&s.xp[wid][8 + nt][0][lane][0], d0);
        xp_store(&s.xp[wid][8 + nt][1][lane][0], d1);
      }
#pragma unroll
      for (int nt = 0; nt < 8; nt++) {
        int n0 = nt * 8 + c2t;
        float d0[4], d1[4];
        d0[0] = s.bq[n0]; d0[1] = s.bq[n0 + 1]; d0[2] = d0[0]; d0[3] = d0[1];
        d1[0] = d0[0]; d1[1] = d0[1]; d1[2] = d0[0]; d1[3] = d0[1];
        gemm12x2(d0, d1, s.wq_x[0], s.wq_x[1], nt, lane, X0H, X0L, X1H, X1L);
        xp_store(&s.xp[wid][16 + nt][0][lane][0], d0);
        xp_store(&s.xp[wid][16 + nt][1][lane][0], d1);
      }
#pragma unroll
      for (int nt = 0; nt < 4; nt++) {
        int n0 = nt * 8 + c2t;
        float d0[4], d1[4];
        d0[0] = s.bd1[n0]; d0[1] = s.bd1[n0 + 1]; d0[2] = d0[0]; d0[3] = d0[1];
        d1[0] = d0[0]; d1[1] = d0[1]; d1[2] = d0[0]; d1[3] = d0[1];
        gemm12x2(d0, d1, s.wd_x[0], s.wd_x[1], nt, lane, X0H, X0L, X1H, X1L);
        xp_store(&s.xp[wid][24 + nt][0][lane][0], d0);
        xp_store(&s.xp[wid][24 + nt][1][lane][0], d1);
      }
    }

    // ---- 4 GRU iterations ----
    float z0[8][4], z1[8][4];
    unsigned R0H[4][4], R0L[4][4], R1H[4][4], R1L[4][4];
#pragma unroll 1
    for (int it = 0; it < 4; it++) {
      // z gate
#pragma unroll
      for (int nt = 0; nt < 8; nt++) {
        float d0[4], d1[4];
        xp_load(d0, &s.xp[wid][nt][0][lane][0]);
        xp_load(d1, &s.xp[wid][nt][1][lane][0]);
        gemm12x2(d0, d1, s.wz_h[0], s.wz_h[1], nt, lane, A0H, A0L, A1H, A1L);
#pragma unroll
        for (int j = 0; j < 4; j++) { z0[nt][j] = sigm(d0[j]); z1[nt][j] = sigm(d1[j]); }
      }
      // r gate -> r*h fragments
#pragma unroll
      for (int nt = 0; nt < 8; nt++) {
        float d0[4], d1[4];
        xp_load(d0, &s.xp[wid][8 + nt][0][lane][0]);
        xp_load(d1, &s.xp[wid][8 + nt][1][lane][0]);
        gemm12x2(d0, d1, s.wr_h[0], s.wr_h[1], nt, lane, A0H, A0L, A1H, A1L);
        int kf = nt >> 1, rA = (nt & 1) * 2, rB = rA + 1;
        // tile 0
        {
          float hA0 = bfl(A0H[kf][rA]) + bfl(A0L[kf][rA]);
          float hA1 = bfh(A0H[kf][rA]) + bfh(A0L[kf][rA]);
          float hB0 = bfl(A0H[kf][rB]) + bfl(A0L[kf][rB]);
          float hB1 = bfh(A0H[kf][rB]) + bfh(A0L[kf][rB]);
          splitp(sigm(d0[0]) * hA0, sigm(d0[1]) * hA1, R0H[kf][rA], R0L[kf][rA]);
          splitp(sigm(d0[2]) * hB0, sigm(d0[3]) * hB1, R0H[kf][rB], R0L[kf][rB]);
        }
        // tile 1
        {
          float hA0 = bfl(A1H[kf][rA]) + bfl(A1L[kf][rA]);
          float hA1 = bfh(A1H[kf][rA]) + bfh(A1L[kf][rA]);
          float hB0 = bfl(A1H[kf][rB]) + bfl(A1L[kf][rB]);
          float hB1 = bfh(A1H[kf][rB]) + bfh(A1L[kf][rB]);
          splitp(sigm(d1[0]) * hA0, sigm(d1[1]) * hA1, R1H[kf][rA], R1L[kf][rA]);
          splitp(sigm(d1[2]) * hB0, sigm(d1[3]) * hB1, R1H[kf][rB], R1L[kf][rB]);
        }
      }
      // q gate + h update (in place in A frags)
#pragma unroll
      for (int nt = 0; nt < 8; nt++) {
        float d0[4], d1[4];
        xp_load(d0, &s.xp[wid][16 + nt][0][lane][0]);
        xp_load(d1, &s.xp[wid][16 + nt][1][lane][0]);
        gemm12x2(d0, d1, s.wq_h[0], s.wq_h[1], nt, lane, R0H, R0L, R1H, R1L);
        int kf = nt >> 1, rA = (nt & 1) * 2, rB = rA + 1;
        // tile 0
        {
          float hA0 = bfl(A0H[kf][rA]) + bfl(A0L[kf][rA]);
          float hA1 = bfh(A0H[kf][rA]) + bfh(A0L[kf][rA]);
          float hB0 = bfl(A0H[kf][rB]) + bfl(A0L[kf][rB]);
          float hB1 = bfh(A0H[kf][rB]) + bfh(A0L[kf][rB]);
          hA0 = fmaf(z0[nt][0], tanhfast(d0[0]) - hA0, hA0);
          hA1 = fmaf(z0[nt][1], tanhfast(d0[1]) - hA1, hA1);
          hB0 = fmaf(z0[nt][2], tanhfast(d0[2]) - hB0, hB0);
          hB1 = fmaf(z0[nt][3], tanhfast(d0[3]) - hB1, hB1);
          splitp(hA0, hA1, A0H[kf][rA], A0L[kf][rA]);
          splitp(hB0, hB1, A0H[kf][rB], A0L[kf][rB]);
        }
        // tile 1
        {
          float hA0 = bfl(A1H[kf][rA]) + bfl(A1L[kf][rA]);
          float hA1 = bfh(A1H[kf][rA]) + bfh(A1L[kf][rA]);
          float hB0 = bfl(A1H[kf][rB]) + bfl(A1L[kf][rB]);
          float hB1 = bfh(A1H[kf][rB]) + bfh(A1L[kf][rB]);
          hA0 = fmaf(z1[nt][0], tanhfast(d1[0]) - hA0, hA0);
          hA1 = fmaf(z1[nt][1], tanhfast(d1[1]) - hA1, hA1);
          hB0 = fmaf(z1[nt][2], tanhfast(d1[2]) - hB0, hB0);
          hB1 = fmaf(z1[nt][3], tanhfast(d1[3]) - hB1, hB1);
          splitp(hA0, hA1, A1H[kf][rA], A1L[kf][rA]);
          splitp(hB0, hB1, A1H[kf][rB], A1L[kf][rB]);
        }
      }
    }

    // ---- decoder: hmid = gelu(Wd1h @ h + xproj_dec) ----
    float hm0[4][4], hm1[4][4];
#pragma unroll
    for (int nt = 0; nt < 4; nt++) {
      float d0[4], d1[4];
      xp_load(d0, &s.xp[wid][24 + nt][0][lane][0]);
      xp_load(d1, &s.xp[wid][24 + nt][1][lane][0]);
      gemm12x2(d0, d1, s.wd_h[0], s.wd_h[1], nt, lane, A0H, A0L, A1H, A1L);
#pragma unroll
      for (int j = 0; j < 4; j++) {
        hm0[nt][j] = 0.5f * d0[j] * (1.0f + erff(d0[j] * 0.70710678118654752f));
        hm1[nt][j] = 0.5f * d1[j] * (1.0f + erff(d1[j] * 0.70710678118654752f));
      }
    }

    // ---- flow = Wd2 @ hmid + bd2, quad reduction ----
    float fA[3] = {0,0,0}, fB[3] = {0,0,0}, fC[3] = {0,0,0}, fD[3] = {0,0,0};
#pragma unroll
    for (int nt = 0; nt < 4; nt++) {
      int n0 = nt * 8 + c2t;
#pragma unroll
      for (int o = 0; o < 3; o++) {
        float w0 = s.Wd2[o * 32 + n0], w1 = s.Wd2[o * 32 + n0 + 1];
        fA[o] += w0 * hm0[nt][0] + w1 * hm0[nt][1];
        fB[o] += w0 * hm0[nt][2] + w1 * hm0[nt][3];
        fC[o] += w0 * hm1[nt][0] + w1 * hm1[nt][1];
        fD[o] += w0 * hm1[nt][2] + w1 * hm1[nt][3];
      }
    }
#pragma unroll
    for (int o = 0; o < 3; o++) {
      fA[o] += __shfl_xor_sync(0xffffffffu, fA[o], 1);
      fA[o] += __shfl_xor_sync(0xffffffffu, fA[o], 2);
      fB[o] += __shfl_xor_sync(0xffffffffu, fB[o], 1);
      fB[o] += __shfl_xor_sync(0xffffffffu, fB[o], 2);
      fC[o] += __shfl_xor_sync(0xffffffffu, fC[o], 1);
      fC[o] += __shfl_xor_sync(0xffffffffu, fC[o], 2);
      fD[o] += __shfl_xor_sync(0xffffffffu, fD[o], 1);
      fD[o] += __shfl_xor_sync(0xffffffffu, fD[o], 2);
    }
    int t = lane & 3;
    if (t < 3) {
      if (vA) out[(size_t)ptA * 3 + t] = fA[t] + s.bd2[t];
      if (vB) out[(size_t)ptB * 3 + t] = fB[t] + s.bd2[t];
      if (vC) out[(size_t)ptC * 3 + t] = fC[t] + s.bd2[t];
      if (vD) out[(size_t)ptD * 3 + t] = fD[t] + s.bd2[t];
    }
  }
}

extern "C" void kernel_launch(void* const* d_in, const int* in_sizes, int n_in,
                              void* d_out, int out_size) {
  const float* before = (const float*)d_in[0];
  const float* after  = (const float*)d_in[1];
  const float* pf     = (const float*)d_in[2];
  const int*   coords = (const int*)d_in[3];     // int32
  const float* Wz  = (const float*)d_in[4];
  const float* bz  = (const float*)d_in[5];
  const float* Wr  = (const float*)d_in[6];
  const float* br  = (const float*)d_in[7];
  const float* Wq  = (const float*)d_in[8];
  const float* bq  = (const float*)d_in[9];
  const float* Wd1 = (const float*)d_in[10];
  const float* bd1 = (const float*)d_in[11];
  const float* Wd2 = (const float*)d_in[12];
  const float* bd2 = (const float*)d_in[13];
  float* out = (float*)d_out;

  int B = in_sizes[0] / (int)(32u * 256u * 256u * 32u);
  if (B < 1) B = 1;
  int total_pts = in_sizes[3] / 3;
  int N = total_pts / B;

  cudaFuncSetAttribute(gru_hmma2_kernel,
                       cudaFuncAttributeMaxDynamicSharedMemorySize,
                       (int)sizeof(Smem));

  gru_hmma2_kernel<<<152, NTHREADS, sizeof(Smem)>>>(
      before, after, pf, coords, Wz, bz, Wr, br, Wq, bq,
      Wd1, bd1, Wd2, bd2, out, N, total_pts);
}

// round 8
// speedup vs baseline: 1.1356x; 1.1356x over previous
#include <cuda_runtime.h>
#include <math.h>
#include <stdint.h>

#define NTHREADS 256
#define NWARPS 8
#define TILE_M 128     // 8 warps x 16 points

// fixed problem geometry
#define C_STRIDE 2097152ULL     // 256*256*32
#define B_STRIDE 67108864ULL    // 32*256*256*32
#define I_STRIDE 8192
#define J_STRIDE 32

// tf32 B-fragment banks: uint2 per (nt,kf,lane): b0 k=kf*8+(lane&3), b1 +4; n = nt*8+lane/4
struct __align__(16) Smem {
  unsigned wz_h[4096];   // nt 0..7, kf 0..7  (16KB)
  unsigned wr_h[4096];
  unsigned wq_h[4096];
  unsigned wz_x[4096];
  unsigned wr_x[4096];
  unsigned wq_x[4096];
  unsigned wd_h[2048];   // nt 0..3
  unsigned wd_x[2048];
  float xp[NWARPS][28][32][4];   // xproj in D layout: z 0-7, r 8-15, q 16-23, dec 24-27
  float bz[64], br[64], bq[64], bd1[32];
  float Wd2[96], bd2[4];
};

__device__ __forceinline__ float sigm(float x) {
  return __fdividef(1.0f, 1.0f + __expf(-x));
}
__device__ __forceinline__ float tanhfast(float x) {
  return __fdividef(2.0f, 1.0f + __expf(-2.0f * x)) - 1.0f;
}
__device__ __forceinline__ unsigned cvt_tf32(float f) {
  unsigned u;
  asm("cvt.rna.tf32.f32 %0, %1;" : "=r"(u) : "f"(f));
  return u;
}

// m16n8k8 tf32 MMA
__device__ __forceinline__ void mma_tf32(float d[4], const unsigned a[4], uint2 b) {
  asm volatile(
    "mma.sync.aligned.m16n8k8.row.col.f32.tf32.tf32.f32 "
    "{%0,%1,%2,%3}, {%4,%5,%6,%7}, {%8,%9}, {%0,%1,%2,%3};"
    : "+f"(d[0]), "+f"(d[1]), "+f"(d[2]), "+f"(d[3])
    : "r"(a[0]), "r"(a[1]), "r"(a[2]), "r"(a[3]), "r"(b.x), "r"(b.y));
}

// K=64 gemm: 8 MMAs, two independent accumulation chains
__device__ __forceinline__ void gemm8(float d[4], const unsigned* bank, int nt, int lane,
                                      const unsigned (&A)[8][4]) {
  const uint2* bk = reinterpret_cast<const uint2*>(bank);
  float e[4] = {0.f, 0.f, 0.f, 0.f};
#pragma unroll
  for (int kf = 0; kf < 8; kf += 2) {
    uint2 b0 = bk[(nt * 8 + kf) * 32 + lane];
    uint2 b1 = bk[(nt * 8 + kf + 1) * 32 + lane];
    mma_tf32(d, A[kf], b0);
    mma_tf32(e, A[kf + 1], b1);
  }
#pragma unroll
  for (int j = 0; j < 4; j++) d[j] += e[j];
}

// D-layout quad (v[0]:(g,n) v[1]:(g,n+1) v[2]:(g+8,n) v[3]:(g+8,n+1), n=nt*8+2c)
// -> A-layout frag for kf=nt (a0:(g,k=8nt+c) a1:(g+8,k) a2:(g,k+4) a3:(g+8,k+4))
__device__ __forceinline__ void d2a_one(unsigned (&Akf)[4], const float v[4], int lane) {
  const int c = lane & 3;
  const int base = lane & ~3;
  const int s1 = base | (c >> 1);
  const int s2 = s1 + 2;
  const bool odd = (c & 1);
  float v0a = __shfl_sync(0xffffffffu, v[0], s1);
  float v1a = __shfl_sync(0xffffffffu, v[1], s1);
  float v2a = __shfl_sync(0xffffffffu, v[2], s1);
  float v3a = __shfl_sync(0xffffffffu, v[3], s1);
  float v0b = __shfl_sync(0xffffffffu, v[0], s2);
  float v1b = __shfl_sync(0xffffffffu, v[1], s2);
  float v2b = __shfl_sync(0xffffffffu, v[2], s2);
  float v3b = __shfl_sync(0xffffffffu, v[3], s2);
  Akf[0] = cvt_tf32(odd ? v1a : v0a);
  Akf[1] = cvt_tf32(odd ? v3a : v2a);
  Akf[2] = cvt_tf32(odd ? v1b : v0b);
  Akf[3] = cvt_tf32(odd ? v3b : v2b);
}

// fill one gate's tf32 B-fragment bank from row-major W[n][128], cols koff..koff+63
__device__ __forceinline__ void fill_frag(unsigned* dst, const float* __restrict__ W,
                                          int koff, int ntn, int tid) {
  int total = ntn * 8 * 32 * 2;
  for (int i = tid; i < total; i += NTHREADS) {
    int w = i & 1;
    int lane = (i >> 1) & 31;
    int kf = (i >> 6) & 7;
    int nt = i >> 9;
    int n = nt * 8 + (lane >> 2);
    int k = kf * 8 + (lane & 3) + w * 4;
    dst[i] = cvt_tf32(W[n * 128 + koff + k]);
  }
}

__global__ __launch_bounds__(NTHREADS, 1)
void gru_tf32_kernel(
    const float* __restrict__ before, const float* __restrict__ after,
    const float* __restrict__ pf, const int* __restrict__ coords,
    const float* __restrict__ Wz, const float* __restrict__ bz,
    const float* __restrict__ Wr, const float* __restrict__ br,
    const float* __restrict__ Wq, const float* __restrict__ bq,
    const float* __restrict__ Wd1, const float* __restrict__ bd1,
    const float* __restrict__ Wd2, const float* __restrict__ bd2,
    float* __restrict__ out, int N, int total_pts)
{
  extern __shared__ char smem_raw[];
  Smem& s = *reinterpret_cast<Smem*>(smem_raw);
  const int tid = threadIdx.x;
  const int wid = tid >> 5, lane = tid & 31;
  const int g = lane >> 2, c = lane & 3;

  // ---- one-time weight fragment prep ----
  fill_frag(s.wz_h, Wz, 0, 8, tid);
  fill_frag(s.wr_h, Wr, 0, 8, tid);
  fill_frag(s.wq_h, Wq, 0, 8, tid);
  fill_frag(s.wz_x, Wz, 64, 8, tid);
  fill_frag(s.wr_x, Wr, 64, 8, tid);
  fill_frag(s.wq_x, Wq, 64, 8, tid);
  fill_frag(s.wd_h, Wd1, 0, 4, tid);
  fill_frag(s.wd_x, Wd1, 64, 4, tid);
  if (tid < 64) { s.bz[tid] = bz[tid]; s.br[tid] = br[tid]; s.bq[tid] = bq[tid]; }
  if (tid < 32) s.bd1[tid] = bd1[tid];
  if (tid < 96) s.Wd2[tid] = Wd2[tid];
  if (tid < 3)  s.bd2[tid] = bd2[tid];
  __syncthreads();

  const int ntiles = (total_pts + TILE_M - 1) / TILE_M;

  for (int tile = blockIdx.x; tile < ntiles; tile += gridDim.x) {
    const int ptA = tile * TILE_M + wid * 16 + g;   // rows 0-7 of warp m16 tile
    const int ptB = ptA + 8;                         // rows 8-15
    const bool vA = ptA < total_pts, vB = ptB < total_pts;
    const int last = total_pts - 1;
    const int pA = vA ? ptA : last, pB = vB ? ptB : last;

    // ---- gather h in D layout (hD[nt][4]) ----
    float hD[8][4];
    {
      const int* ccA = coords + (size_t)pA * 3;
      const int* ccB = coords + (size_t)pB * 3;
      int spA = ccA[0] * I_STRIDE + ccA[1] * J_STRIDE + ccA[2];
      int spB = ccB[0] * I_STRIDE + ccB[1] * J_STRIDE + ccB[2];
      const float* befA = before + (size_t)(pA / N) * B_STRIDE + (unsigned)spA;
      const float* aftA = after  + (size_t)(pA / N) * B_STRIDE + (unsigned)spA;
      const float* befB = before + (size_t)(pB / N) * B_STRIDE + (unsigned)spB;
      const float* aftB = after  + (size_t)(pB / N) * B_STRIDE + (unsigned)spB;
#pragma unroll
      for (int nt = 0; nt < 8; nt++) {
        int cb = (nt & 3) * 8 + 2 * c;     // channel base
        const float* pa = (nt < 4) ? befA : aftA;
        const float* pb = (nt < 4) ? befB : aftB;
        hD[nt][0] = __ldg(pa + (size_t)cb * C_STRIDE);
        hD[nt][1] = __ldg(pa + (size_t)(cb + 1) * C_STRIDE);
        hD[nt][2] = __ldg(pb + (size_t)cb * C_STRIDE);
        hD[nt][3] = __ldg(pb + (size_t)(cb + 1) * C_STRIDE);
      }
    }

    // ---- h into A-layout tf32 frags ----
    unsigned A[8][4];
#pragma unroll
    for (int nt = 0; nt < 8; nt++) d2a_one(A[nt], hD[nt], lane);

    // ---- x A-frags + x-projection GEMMs -> fp32 smem dumps ----
    {
      unsigned XA[8][4];
      const float* xA = pf + (size_t)pA * 64;
      const float* xB = pf + (size_t)pB * 64;
#pragma unroll
      for (int kf = 0; kf < 8; kf++) {
        XA[kf][0] = cvt_tf32(__ldg(xA + kf * 8 + c));
        XA[kf][1] = cvt_tf32(__ldg(xB + kf * 8 + c));
        XA[kf][2] = cvt_tf32(__ldg(xA + kf * 8 + c + 4));
        XA[kf][3] = cvt_tf32(__ldg(xB + kf * 8 + c + 4));
      }
#pragma unroll
      for (int nt = 0; nt < 8; nt++) {
        int n0 = nt * 8 + 2 * c;
        float d[4];
        d[0] = s.bz[n0]; d[1] = s.bz[n0 + 1]; d[2] = d[0]; d[3] = d[1];
        gemm8(d, s.wz_x, nt, lane, XA);
        *(float4*)&s.xp[wid][nt][lane][0] = make_float4(d[0], d[1], d[2], d[3]);
      }
#pragma unroll
      for (int nt = 0; nt < 8; nt++) {
        int n0 = nt * 8 + 2 * c;
        float d[4];
        d[0] = s.br[n0]; d[1] = s.br[n0 + 1]; d[2] = d[0]; d[3] = d[1];
        gemm8(d, s.wr_x, nt, lane, XA);
        *(float4*)&s.xp[wid][8 + nt][lane][0] = make_float4(d[0], d[1], d[2], d[3]);
      }
#pragma unroll
      for (int nt = 0; nt < 8; nt++) {
        int n0 = nt * 8 + 2 * c;
        float d[4];
        d[0] = s.bq[n0]; d[1] = s.bq[n0 + 1]; d[2] = d[0]; d[3] = d[1];
        gemm8(d, s.wq_x, nt, lane, XA);
        *(float4*)&s.xp[wid][16 + nt][lane][0] = make_float4(d[0], d[1], d[2], d[3]);
      }
#pragma unroll
      for (int nt = 0; nt < 4; nt++) {
        int n0 = nt * 8 + 2 * c;
        float d[4];
        d[0] = s.bd1[n0]; d[1] = s.bd1[n0 + 1]; d[2] = d[0]; d[3] = d[1];
        gemm8(d, s.wd_x, nt, lane, XA);
        *(float4*)&s.xp[wid][24 + nt][lane][0] = make_float4(d[0], d[1], d[2], d[3]);
      }
    }

    // ---- 4 GRU iterations ----
    float z[8][4];
    unsigned R[8][4];
#pragma unroll 1
    for (int it = 0; it < 4; it++) {
      // z gate (reads A)
#pragma unroll
      for (int nt = 0; nt < 8; nt++) {
        float4 dv = *(const float4*)&s.xp[wid][nt][lane][0];
        float d[4] = {dv.x, dv.y, dv.z, dv.w};
        gemm8(d, s.wz_h, nt, lane, A);
#pragma unroll
        for (int j = 0; j < 4; j++) z[nt][j] = sigm(d[j]);
      }
      // r gate (reads A) -> R = tf32(r*h) in A layout
#pragma unroll
      for (int nt = 0; nt < 8; nt++) {
        float4 dv = *(const float4*)&s.xp[wid][8 + nt][lane][0];
        float d[4] = {dv.x, dv.y, dv.z, dv.w};
        gemm8(d, s.wr_h, nt, lane, A);
        float rh[4];
#pragma unroll
        for (int j = 0; j < 4; j++) rh[j] = sigm(d[j]) * hD[nt][j];
        d2a_one(R[nt], rh, lane);
      }
      // q gate (reads R) -> hD update -> A refresh
#pragma unroll
      for (int nt = 0; nt < 8; nt++) {
        float4 dv = *(const float4*)&s.xp[wid][16 + nt][lane][0];
        float d[4] = {dv.x, dv.y, dv.z, dv.w};
        gemm8(d, s.wq_h, nt, lane, R);
#pragma unroll
        for (int j = 0; j < 4; j++)
          hD[nt][j] = fmaf(z[nt][j], tanhfast(d[j]) - hD[nt][j], hD[nt][j]);
        d2a_one(A[nt], hD[nt], lane);
      }
    }

    // ---- decoder: hmid = gelu(Wd1h @ h + xproj_dec) ----
    float hm[4][4];
#pragma unroll
    for (int nt = 0; nt < 4; nt++) {
      float4 dv = *(const float4*)&s.xp[wid][24 + nt][lane][0];
      float d[4] = {dv.x, dv.y, dv.z, dv.w};
      gemm8(d, s.wd_h, nt, lane, A);
#pragma unroll
      for (int j = 0; j < 4; j++)
        hm[nt][j] = 0.5f * d[j] * (1.0f + erff(d[j] * 0.70710678118654752f));
    }

    // ---- flow = Wd2 @ hmid + bd2, quad reduction ----
    float fA[3] = {0.f, 0.f, 0.f}, fB[3] = {0.f, 0.f, 0.f};
#pragma unroll
    for (int nt = 0; nt < 4; nt++) {
      int n0 = nt * 8 + 2 * c;
#pragma unroll
      for (int o = 0; o < 3; o++) {
        float w0 = s.Wd2[o * 32 + n0], w1 = s.Wd2[o * 32 + n0 + 1];
        fA[o] += w0 * hm[nt][0] + w1 * hm[nt][1];
        fB[o] += w0 * hm[nt][2] + w1 * hm[nt][3];
      }
    }
#pragma unroll
    for (int o = 0; o < 3; o++) {
      fA[o] += __shfl_xor_sync(0xffffffffu, fA[o], 1);
      fA[o] += __shfl_xor_sync(0xffffffffu, fA[o], 2);
      fB[o] += __shfl_xor_sync(0xffffffffu, fB[o], 1);
      fB[o] += __shfl_xor_sync(0xffffffffu, fB[o], 2);
    }
    int t = c;
    if (t < 3) {
      if (vA) out[(size_t)ptA * 3 + t] = fA[t] + s.bd2[t];
      if (vB) out[(size_t)ptB * 3 + t] = fB[t] + s.bd2[t];
    }
  }
}

extern "C" void kernel_launch(void* const* d_in, const int* in_sizes, int n_in,
                              void* d_out, int out_size) {
  const float* before = (const float*)d_in[0];
  const float* after  = (const float*)d_in[1];
  const float* pf     = (const float*)d_in[2];
  const int*   coords = (const int*)d_in[3];     // int32
  const float* Wz  = (const float*)d_in[4];
  const float* bz  = (const float*)d_in[5];
  const float* Wr  = (const float*)d_in[6];
  const float* br  = (const float*)d_in[7];
  const float* Wq  = (const float*)d_in[8];
  const float* bq  = (const float*)d_in[9];
  const float* Wd1 = (const float*)d_in[10];
  const float* bd1 = (const float*)d_in[11];
  const float* Wd2 = (const float*)d_in[12];
  const float* bd2 = (const float*)d_in[13];
  float* out = (float*)d_out;

  int B = in_sizes[0] / (int)(32u * 256u * 256u * 32u);
  if (B < 1) B = 1;
  int total_pts = in_sizes[3] / 3;
  int N = total_pts / B;

  cudaFuncSetAttribute(gru_tf32_kernel,
                       cudaFuncAttributeMaxDynamicSharedMemorySize,
                       (int)sizeof(Smem));

  gru_tf32_kernel<<<152, NTHREADS, sizeof(Smem)>>>(
      before, after, pf, coords, Wz, bz, Wr, br, Wq, bq,
      Wd1, bd1, Wd2, bd2, out, N, total_pts);
}

// round 9
// speedup vs baseline: 1.1510x; 1.0135x over previous
#include <cuda_runtime.h>
#include <math.h>
#include <stdint.h>

#define NTHREADS 256
#define NWARPS 8
#define TILE_M 128     // 8 warps x 16 points

// fixed problem geometry
#define C_STRIDE 2097152ULL     // 256*256*32
#define B_STRIDE 67108864ULL    // 32*256*256*32
#define I_STRIDE 8192
#define J_STRIDE 32

// tf32 B-fragment banks: uint2 per (nt,kf,lane): b0 k=kf*8+(lane&3), b1 +4; n = nt*8+lane/4
struct __align__(16) Smem {
  unsigned wz_h[4096];   // nt 0..7, kf 0..7  (16KB)
  unsigned wr_h[4096];
  unsigned wq_h[4096];
  unsigned wz_x[4096];
  unsigned wr_x[4096];
  unsigned wq_x[4096];
  unsigned wd_h[2048];   // nt 0..3
  unsigned wd_x[2048];
  float xp[NWARPS][28][32][4];   // xproj in D layout: z 0-7, r 8-15, q 16-23, dec 24-27
  float bz[64], br[64], bq[64], bd1[32];
  float Wd2[96], bd2[4];
};

__device__ __forceinline__ float tanh_hw(float x) {
  float y;
  asm("tanh.approx.f32 %0, %1;" : "=f"(y) : "f"(x));
  return y;
}
__device__ __forceinline__ float sigm(float x) {
  return fmaf(0.5f, tanh_hw(0.5f * x), 0.5f);
}
__device__ __forceinline__ unsigned cvt_tf32(float f) {
  unsigned u;
  asm("cvt.rna.tf32.f32 %0, %1;" : "=r"(u) : "f"(f));
  return u;
}

// m16n8k8 tf32 MMA
__device__ __forceinline__ void mma_tf32(float d[4], const unsigned a[4], uint2 b) {
  asm volatile(
    "mma.sync.aligned.m16n8k8.row.col.f32.tf32.tf32.f32 "
    "{%0,%1,%2,%3}, {%4,%5,%6,%7}, {%8,%9}, {%0,%1,%2,%3};"
    : "+f"(d[0]), "+f"(d[1]), "+f"(d[2]), "+f"(d[3])
    : "r"(a[0]), "r"(a[1]), "r"(a[2]), "r"(a[3]), "r"(b.x), "r"(b.y));
}

// K=64 gemm: 8 MMAs, four independent accumulation chains
__device__ __forceinline__ void gemm8(float d[4], const unsigned* bank, int nt, int lane,
                                      const unsigned (&A)[8][4]) {
  const uint2* bk = reinterpret_cast<const uint2*>(bank) + (nt * 8) * 32 + lane;
  float e[4] = {0.f, 0.f, 0.f, 0.f};
  float f[4] = {0.f, 0.f, 0.f, 0.f};
  float g[4] = {0.f, 0.f, 0.f, 0.f};
  uint2 b0 = bk[0 * 32], b1 = bk[1 * 32], b2 = bk[2 * 32], b3 = bk[3 * 32];
  uint2 b4 = bk[4 * 32], b5 = bk[5 * 32], b6 = bk[6 * 32], b7 = bk[7 * 32];
  mma_tf32(d, A[0], b0); mma_tf32(e, A[1], b1);
  mma_tf32(f, A[2], b2); mma_tf32(g, A[3], b3);
  mma_tf32(d, A[4], b4); mma_tf32(e, A[5], b5);
  mma_tf32(f, A[6], b6); mma_tf32(g, A[7], b7);
#pragma unroll
  for (int j = 0; j < 4; j++) d[j] += (e[j] + f[j]) + g[j];
}

// D-layout quad -> A-layout frag for kf=nt
__device__ __forceinline__ void d2a_one(unsigned (&Akf)[4], const float v[4], int lane) {
  const int c = lane & 3;
  const int base = lane & ~3;
  const int s1 = base | (c >> 1);
  const int s2 = s1 + 2;
  const bool odd = (c & 1);
  float v0a = __shfl_sync(0xffffffffu, v[0], s1);
  float v1a = __shfl_sync(0xffffffffu, v[1], s1);
  float v2a = __shfl_sync(0xffffffffu, v[2], s1);
  float v3a = __shfl_sync(0xffffffffu, v[3], s1);
  float v0b = __shfl_sync(0xffffffffu, v[0], s2);
  float v1b = __shfl_sync(0xffffffffu, v[1], s2);
  float v2b = __shfl_sync(0xffffffffu, v[2], s2);
  float v3b = __shfl_sync(0xffffffffu, v[3], s2);
  Akf[0] = cvt_tf32(odd ? v1a : v0a);
  Akf[1] = cvt_tf32(odd ? v3a : v2a);
  Akf[2] = cvt_tf32(odd ? v1b : v0b);
  Akf[3] = cvt_tf32(odd ? v3b : v2b);
}

// fill one gate's tf32 B-fragment bank from row-major W[n][128], cols koff..koff+63
__device__ __forceinline__ void fill_frag(unsigned* dst, const float* __restrict__ W,
                                          int koff, int ntn, int tid) {
  int total = ntn * 8 * 32 * 2;
  for (int i = tid; i < total; i += NTHREADS) {
    int w = i & 1;
    int lane = (i >> 1) & 31;
    int kf = (i >> 6) & 7;
    int nt = i >> 9;
    int n = nt * 8 + (lane >> 2);
    int k = kf * 8 + (lane & 3) + w * 4;
    dst[i] = cvt_tf32(W[n * 128 + koff + k]);
  }
}

__global__ __launch_bounds__(NTHREADS, 1)
void gru_tf32_kernel(
    const float* __restrict__ before, const float* __restrict__ after,
    const float* __restrict__ pf, const int* __restrict__ coords,
    const float* __restrict__ Wz, const float* __restrict__ bz,
    const float* __restrict__ Wr, const float* __restrict__ br,
    const float* __restrict__ Wq, const float* __restrict__ bq,
    const float* __restrict__ Wd1, const float* __restrict__ bd1,
    const float* __restrict__ Wd2, const float* __restrict__ bd2,
    float* __restrict__ out, int N, int total_pts)
{
  extern __shared__ char smem_raw[];
  Smem& s = *reinterpret_cast<Smem*>(smem_raw);
  const int tid = threadIdx.x;
  const int wid = tid >> 5, lane = tid & 31;
  const int g = lane >> 2, c = lane & 3;

  // ---- one-time weight fragment prep ----
  fill_frag(s.wz_h, Wz, 0, 8, tid);
  fill_frag(s.wr_h, Wr, 0, 8, tid);
  fill_frag(s.wq_h, Wq, 0, 8, tid);
  fill_frag(s.wz_x, Wz, 64, 8, tid);
  fill_frag(s.wr_x, Wr, 64, 8, tid);
  fill_frag(s.wq_x, Wq, 64, 8, tid);
  fill_frag(s.wd_h, Wd1, 0, 4, tid);
  fill_frag(s.wd_x, Wd1, 64, 4, tid);
  if (tid < 64) { s.bz[tid] = bz[tid]; s.br[tid] = br[tid]; s.bq[tid] = bq[tid]; }
  if (tid < 32) s.bd1[tid] = bd1[tid];
  if (tid < 96) s.Wd2[tid] = Wd2[tid];
  if (tid < 3)  s.bd2[tid] = bd2[tid];
  __syncthreads();

  const int ntiles = (total_pts + TILE_M - 1) / TILE_M;

  for (int tile = blockIdx.x; tile < ntiles; tile += gridDim.x) {
    const int ptA = tile * TILE_M + wid * 16 + g;   // rows 0-7 of warp m16 tile
    const int ptB = ptA + 8;                         // rows 8-15
    const bool vA = ptA < total_pts, vB = ptB < total_pts;
    const int last = total_pts - 1;
    const int pA = vA ? ptA : last, pB = vB ? ptB : last;

    // ---- gather h in D layout (hD[nt][4]) ----
    float hD[8][4];
    {
      const int* ccA = coords + (size_t)pA * 3;
      const int* ccB = coords + (size_t)pB * 3;
      int spA = ccA[0] * I_STRIDE + ccA[1] * J_STRIDE + ccA[2];
      int spB = ccB[0] * I_STRIDE + ccB[1] * J_STRIDE + ccB[2];
      const float* befA = before + (size_t)(pA / N) * B_STRIDE + (unsigned)spA;
      const float* aftA = after  + (size_t)(pA / N) * B_STRIDE + (unsigned)spA;
      const float* befB = before + (size_t)(pB / N) * B_STRIDE + (unsigned)spB;
      const float* aftB = after  + (size_t)(pB / N) * B_STRIDE + (unsigned)spB;
#pragma unroll
      for (int nt = 0; nt < 8; nt++) {
        int cb = (nt & 3) * 8 + 2 * c;     // channel base
        const float* pa = (nt < 4) ? befA : aftA;
        const float* pb = (nt < 4) ? befB : aftB;
        hD[nt][0] = __ldg(pa + (size_t)cb * C_STRIDE);
        hD[nt][1] = __ldg(pa + (size_t)(cb + 1) * C_STRIDE);
        hD[nt][2] = __ldg(pb + (size_t)cb * C_STRIDE);
        hD[nt][3] = __ldg(pb + (size_t)(cb + 1) * C_STRIDE);
      }
    }

    // ---- h into A-layout tf32 frags ----
    unsigned A[8][4];
#pragma unroll
    for (int nt = 0; nt < 8; nt++) d2a_one(A[nt], hD[nt], lane);

    // ---- x A-frags + x-projection GEMMs -> fp32 smem dumps ----
    {
      unsigned XA[8][4];
      const float* xA = pf + (size_t)pA * 64;
      const float* xB = pf + (size_t)pB * 64;
#pragma unroll
      for (int kf = 0; kf < 8; kf++) {
        XA[kf][0] = cvt_tf32(__ldg(xA + kf * 8 + c));
        XA[kf][1] = cvt_tf32(__ldg(xB + kf * 8 + c));
        XA[kf][2] = cvt_tf32(__ldg(xA + kf * 8 + c + 4));
        XA[kf][3] = cvt_tf32(__ldg(xB + kf * 8 + c + 4));
      }
#pragma unroll
      for (int nt = 0; nt < 8; nt++) {
        int n0 = nt * 8 + 2 * c;
        float d[4];
        d[0] = s.bz[n0]; d[1] = s.bz[n0 + 1]; d[2] = d[0]; d[3] = d[1];
        gemm8(d, s.wz_x, nt, lane, XA);
        *(float4*)&s.xp[wid][nt][lane][0] = make_float4(d[0], d[1], d[2], d[3]);
      }
#pragma unroll
      for (int nt = 0; nt < 8; nt++) {
        int n0 = nt * 8 + 2 * c;
        float d[4];
        d[0] = s.br[n0]; d[1] = s.br[n0 + 1]; d[2] = d[0]; d[3] = d[1];
        gemm8(d, s.wr_x, nt, lane, XA);
        *(float4*)&s.xp[wid][8 + nt][lane][0] = make_float4(d[0], d[1], d[2], d[3]);
      }
#pragma unroll
      for (int nt = 0; nt < 8; nt++) {
        int n0 = nt * 8 + 2 * c;
        float d[4];
        d[0] = s.bq[n0]; d[1] = s.bq[n0 + 1]; d[2] = d[0]; d[3] = d[1];
        gemm8(d, s.wq_x, nt, lane, XA);
        *(float4*)&s.xp[wid][16 + nt][lane][0] = make_float4(d[0], d[1], d[2], d[3]);
      }
#pragma unroll
      for (int nt = 0; nt < 4; nt++) {
        int n0 = nt * 8 + 2 * c;
        float d[4];
        d[0] = s.bd1[n0]; d[1] = s.bd1[n0 + 1]; d[2] = d[0]; d[3] = d[1];
        gemm8(d, s.wd_x, nt, lane, XA);
        *(float4*)&s.xp[wid][24 + nt][lane][0] = make_float4(d[0], d[1], d[2], d[3]);
      }
    }

    // ---- 4 GRU iterations ----
    float z[8][4];
    unsigned R[8][4];
#pragma unroll 1
    for (int it = 0; it < 4; it++) {
      // fused z + r gates (both read A)
#pragma unroll
      for (int nt = 0; nt < 8; nt++) {
        float4 zv = *(const float4*)&s.xp[wid][nt][lane][0];
        float4 rv = *(const float4*)&s.xp[wid][8 + nt][lane][0];
        float dz[4] = {zv.x, zv.y, zv.z, zv.w};
        float dr[4] = {rv.x, rv.y, rv.z, rv.w};
        gemm8(dz, s.wz_h, nt, lane, A);
        gemm8(dr, s.wr_h, nt, lane, A);
        float rh[4];
#pragma unroll
        for (int j = 0; j < 4; j++) {
          z[nt][j] = sigm(dz[j]);
          rh[j] = sigm(dr[j]) * hD[nt][j];
        }
        d2a_one(R[nt], rh, lane);
      }
      // q gate (reads R) -> hD update -> A refresh
#pragma unroll
      for (int nt = 0; nt < 8; nt++) {
        float4 dv = *(const float4*)&s.xp[wid][16 + nt][lane][0];
        float d[4] = {dv.x, dv.y, dv.z, dv.w};
        gemm8(d, s.wq_h, nt, lane, R);
#pragma unroll
        for (int j = 0; j < 4; j++)
          hD[nt][j] = fmaf(z[nt][j], tanh_hw(d[j]) - hD[nt][j], hD[nt][j]);
        d2a_one(A[nt], hD[nt], lane);
      }
    }

    // ---- decoder: hmid = gelu(Wd1h @ h + xproj_dec) ----
    float hm[4][4];
#pragma unroll
    for (int nt = 0; nt < 4; nt++) {
      float4 dv = *(const float4*)&s.xp[wid][24 + nt][lane][0];
      float d[4] = {dv.x, dv.y, dv.z, dv.w};
      gemm8(d, s.wd_h, nt, lane, A);
#pragma unroll
      for (int j = 0; j < 4; j++)
        hm[nt][j] = 0.5f * d[j] * (1.0f + erff(d[j] * 0.70710678118654752f));
    }

    // ---- flow = Wd2 @ hmid + bd2, quad reduction ----
    float fA[3] = {0.f, 0.f, 0.f}, fB[3] = {0.f, 0.f, 0.f};
#pragma unroll
    for (int nt = 0; nt < 4; nt++) {
      int n0 = nt * 8 + 2 * c;
#pragma unroll
      for (int o = 0; o < 3; o++) {
        float w0 = s.Wd2[o * 32 + n0], w1 = s.Wd2[o * 32 + n0 + 1];
        fA[o] += w0 * hm[nt][0] + w1 * hm[nt][1];
        fB[o] += w0 * hm[nt][2] + w1 * hm[nt][3];
      }
    }
#pragma unroll
    for (int o = 0; o < 3; o++) {
      fA[o] += __shfl_xor_sync(0xffffffffu, fA[o], 1);
      fA[o] += __shfl_xor_sync(0xffffffffu, fA[o], 2);
      fB[o] += __shfl_xor_sync(0xffffffffu, fB[o], 1);
      fB[o] += __shfl_xor_sync(0xffffffffu, fB[o], 2);
    }
    if (c < 3) {
      if (vA) out[(size_t)ptA * 3 + c] = fA[c] + s.bd2[c];
      if (vB) out[(size_t)ptB * 3 + c] = fB[c] + s.bd2[c];
    }
  }
}

extern "C" void kernel_launch(void* const* d_in, const int* in_sizes, int n_in,
                              void* d_out, int out_size) {
  const float* before = (const float*)d_in[0];
  const float* after  = (const float*)d_in[1];
  const float* pf     = (const float*)d_in[2];
  const int*   coords = (const int*)d_in[3];     // int32
  const float* Wz  = (const float*)d_in[4];
  const float* bz  = (const float*)d_in[5];
  const float* Wr  = (const float*)d_in[6];
  const float* br  = (const float*)d_in[7];
  const float* Wq  = (const float*)d_in[8];
  const float* bq  = (const float*)d_in[9];
  const float* Wd1 = (const float*)d_in[10];
  const float* bd1 = (const float*)d_in[11];
  const float* Wd2 = (const float*)d_in[12];
  const float* bd2 = (const float*)d_in[13];
  float* out = (float*)d_out;

  int B = in_sizes[0] / (int)(32u * 256u * 256u * 32u);
  if (B < 1) B = 1;
  int total_pts = in_sizes[3] / 3;
  int N = total_pts / B;

  cudaFuncSetAttribute(gru_tf32_kernel,
                       cudaFuncAttributeMaxDynamicSharedMemorySize,
                       (int)sizeof(Smem));

  gru_tf32_kernel<<<152, NTHREADS, sizeof(Smem)>>>(
      before, after, pf, coords, Wz, bz, Wr, br, Wq, bq,
      Wd1, bd1, Wd2, bd2, out, N, total_pts);
}